// round 8
// baseline (speedup 1.0000x reference)
#include <cuda_runtime.h>
#include <cuda_fp16.h>

// CapsuleLayer dynamic routing, GB300 sm_103a.
// B=64, I=2048, Din=16, J=32, D=32, 3 routing iters.
//
// b_k[b,j,i] = osum_k[b,j,:] . u_hat[b,j,i,:]; each routing iteration is one
// streaming pass over fp16 u_hat + (inlined) squash. Iteration 0: c == 1/32.
// Route passes stream u_hat through PER-WARP 4-stage cp.async rings: each lane
// consumes exactly the bytes it loaded itself, so no __syncthreads in the hot
// loop; ordering is per-thread cp.async.wait_group. A group is committed every
// iteration (empty in the tail) to keep wait_group<2> aligned.
// g_spart is double-buffered: route0 -> [0], route1 reads[0] writes[1],
// route2 reads[1] writes[0], final squash reads [0].

#define BB 64
#define II 2048
#define CC 16
#define JJ 32
#define DD 32
#define NTILE 16   // i-tiles (blocks) per b; block covers 128 i
#define NSTAGE 4   // per-warp ring stages (1 i = 2KB per stage)
#define NITER 16   // i per warp

typedef unsigned long long u64;

__device__ __half g_U[(size_t)BB * II * JJ * DD];     // 256 MB scratch (fp16)
__device__ float g_osum[BB * JJ * DD];                // osum after iter k
__device__ float g_spart[2][NTILE][BB * JJ * DD];     // double-buffered partials

// ---------- packed fp32x2 helpers ----------
__device__ __forceinline__ u64 fma2(u64 a, u64 b, u64 c) {
    u64 d;
    asm("fma.rn.f32x2 %0, %1, %2, %3;" : "=l"(d) : "l"(a), "l"(b), "l"(c));
    return d;
}
__device__ __forceinline__ u64 add2(u64 a, u64 b) {
    u64 d;
    asm("add.rn.f32x2 %0, %1, %2;" : "=l"(d) : "l"(a), "l"(b));
    return d;
}
__device__ __forceinline__ float hsum2(u64 v) {
    float a, b;
    asm("mov.b64 {%0, %1}, %2;" : "=f"(a), "=f"(b) : "l"(v));
    return a + b;
}

// ---------- cp.async helpers ----------
__device__ __forceinline__ void cpasync16(unsigned smem_addr, const void* g) {
    asm volatile("cp.async.cg.shared.global [%0], [%1], 16;" ::"r"(smem_addr),
                 "l"(g));
}
__device__ __forceinline__ void cpcommit() {
    asm volatile("cp.async.commit_group;");
}
template <int N>
__device__ __forceinline__ void cpwait() {
    asm volatile("cp.async.wait_group %0;" ::"n"(N));
}

// ---------------------------------------------------------------------------
// Kernel A: u_hat[b][i][j][d] = sum_c W[j][i][d][c] * x[b][i][c], fp16.
// One block per i. W chunk-major in smem (8 contiguous LDS.128 per (j,thread),
// conflict-free). Thread (bg = t>>4, q = t&15): 4 batches, d = 2q, 2q+1.
// ---------------------------------------------------------------------------
__global__ void __launch_bounds__(256, 2)
uhat_kernel(const float* __restrict__ x, const float* __restrict__ W) {
    extern __shared__ __align__(16) char smraw[];
    float2* sW = reinterpret_cast<float2*>(smraw);        // [8][1024] = 64KB
    float* sX = reinterpret_cast<float*>(smraw + 65536);  // [64][16]  = 4KB
    const int i = blockIdx.x;
    const int t = threadIdx.x;

    const float4* Wg = reinterpret_cast<const float4*>(W);
    #pragma unroll
    for (int k = 0; k < 16; k++) {
        int v = t + 256 * k;
        int row = v >> 2, ch = v & 3;  // row = j*32 + d
        int j = row >> 5, d = row & 31;
        float4 f = Wg[(size_t)(j * II + i) * 128 + d * 4 + ch];
        sW[(2 * ch) * 1024 + row] = make_float2(f.x, f.y);
        sW[(2 * ch + 1) * 1024 + row] = make_float2(f.z, f.w);
    }
    {
        int b = t >> 2, r = t & 3;
        reinterpret_cast<float4*>(sX)[t] =
            reinterpret_cast<const float4*>(x)[(size_t)(b * II + i) * 4 + r];
    }
    __syncthreads();

    const int bg = t >> 4, q = t & 15;
    u64 xr[4][8];
    #pragma unroll
    for (int s = 0; s < 4; s++) {
        const u64* xp = reinterpret_cast<const u64*>(sX + (bg + 16 * s) * CC);
        #pragma unroll
        for (int k = 0; k < 8; k++) xr[s][k] = xp[k];
    }

    __half2* Uo = reinterpret_cast<__half2*>(g_U);
    const float4* sW4 = reinterpret_cast<const float4*>(sW);
    for (int j = 0; j < JJ; j++) {
        u64 w0[8], w1[8];
        #pragma unroll
        for (int k = 0; k < 8; k++) {
            float4 wv = sW4[k * 512 + j * 16 + q];
            const u64* pv = reinterpret_cast<const u64*>(&wv);
            w0[k] = pv[0];  // d = 2q
            w1[k] = pv[1];  // d = 2q+1
        }
        #pragma unroll
        for (int s = 0; s < 4; s++) {
            u64 a0 = 0ULL, a1 = 0ULL, b0 = 0ULL, b1 = 0ULL;
            #pragma unroll
            for (int k = 0; k < 8; k += 2) {
                a0 = fma2(w0[k],     xr[s][k],     a0);
                a1 = fma2(w0[k + 1], xr[s][k + 1], a1);
                b0 = fma2(w1[k],     xr[s][k],     b0);
                b1 = fma2(w1[k + 1], xr[s][k + 1], b1);
            }
            float d0 = hsum2(add2(a0, a1));
            float d1 = hsum2(add2(b0, b1));
            int b = bg + 16 * s;
            Uo[(size_t)(b * II + i) * 512 + j * 16 + q] = __floats2half2_rn(d0, d1);
        }
    }
}

// ---------------------------------------------------------------------------
// Route compute step: lane l chunk m (uint4 = 8 halfs) holds j = 8m + (l>>2),
// d-seg (l&3)*8..+7. Logit reduce over 4-lane groups; softmax over 32 j via
// in-thread + xor 4,8,16.
// ---------------------------------------------------------------------------
__device__ __forceinline__ void cvt8(const uint4& r, float* uf) {
    const __half2* h = reinterpret_cast<const __half2*>(&r);
    #pragma unroll
    for (int p = 0; p < 4; p++) {
        float2 f = __half22float2(h[p]);
        uf[2 * p] = f.x;
        uf[2 * p + 1] = f.y;
    }
}

template <int MODE>
__device__ __forceinline__ void route_step(const uint4* r, const float ov[4][8],
                                           float sacc[4][8]) {
    float uf[4][8];
    #pragma unroll
    for (int m = 0; m < 4; m++) cvt8(r[m], uf[m]);
    float c[4];
    if (MODE == 0) {
        #pragma unroll
        for (int m = 0; m < 4; m++) c[m] = 0.03125f;
    } else {
        float tp[4];
        #pragma unroll
        for (int m = 0; m < 4; m++) {
            float a = uf[m][0] * ov[m][0];
            #pragma unroll
            for (int k = 1; k < 8; k++) a = fmaf(uf[m][k], ov[m][k], a);
            tp[m] = a;
        }
        #pragma unroll
        for (int s = 1; s < 4; s <<= 1)
            #pragma unroll
            for (int m = 0; m < 4; m++)
                tp[m] += __shfl_xor_sync(0xffffffffu, tp[m], s);
        float e[4], ss = 0.f;
        #pragma unroll
        for (int m = 0; m < 4; m++) {
            e[m] = __expf(tp[m]);
            ss += e[m];
        }
        ss += __shfl_xor_sync(0xffffffffu, ss, 4);
        ss += __shfl_xor_sync(0xffffffffu, ss, 8);
        ss += __shfl_xor_sync(0xffffffffu, ss, 16);
        float inv = __fdividef(1.0f, ss);
        #pragma unroll
        for (int m = 0; m < 4; m++) c[m] = e[m] * inv;
    }
    #pragma unroll
    for (int m = 0; m < 4; m++)
        #pragma unroll
        for (int k = 0; k < 8; k++) sacc[m][k] = fmaf(c[m], uf[m][k], sacc[m][k]);
}

// ---------------------------------------------------------------------------
// Kernel B: one routing pass. grid = (NTILE, BB), 256 thr, per-warp 4-stage
// cp.async ring (1 i = 2KB per stage; lane consumes its own loaded bytes ->
// no barriers in the hot loop).
// MODE 0: c = 1/32, no prologue. MODE 1: osum = squash(sum spart[SRC]);
// itile==0 block persists it to g_osum. MODE 2: osum = g_osum + squash(...).
// Writes partials to g_spart[1-SRC... i.e. DST]. DIR reverses traversal.
// ---------------------------------------------------------------------------
template <int MODE, int DIR, int SRC, int DST>
__global__ void __launch_bounds__(256, 2) route_kernel() {
    extern __shared__ __align__(16) char dsm[];
    __half* sU = reinterpret_cast<__half*>(dsm);                // 8 warps * 8KB
    float* sS = reinterpret_cast<float*>(dsm + 65536);          // 8*1024 floats
    float* sO = sS;                                             // prologue reuse

    const int itile = DIR ? (NTILE - 1 - (int)blockIdx.x) : (int)blockIdx.x;
    const int b = DIR ? (BB - 1 - (int)blockIdx.y) : (int)blockIdx.y;
    const int t = threadIdx.x, w = t >> 5, l = t & 31;

    float ov[4][8];
    if (MODE > 0) {
        // inline squash: osum for this b, computed identically by all blocks
        for (int idx = t; idx < JJ * DD; idx += 256) {
            float v = 0.f;
            #pragma unroll
            for (int it = 0; it < NTILE; it++)
                v += g_spart[SRC][it][b * (JJ * DD) + idx];
            sO[idx] = v;
        }
        __syncthreads();
        #pragma unroll
        for (int jj = 0; jj < 4; jj++) {
            int j = w * 4 + jj;
            float v = sO[j * DD + l];
            float s2 = v * v;
            #pragma unroll
            for (int s = 1; s < 32; s <<= 1)
                s2 += __shfl_xor_sync(0xffffffffu, s2, s);
            float scale = (s2 / (1.0f + s2)) * rsqrtf(s2 + 1e-7f);
            float o = scale * v;
            if (MODE == 2) o += g_osum[b * (JJ * DD) + j * DD + l];
            sO[j * DD + l] = o;
        }
        __syncthreads();
        if (MODE == 1 && itile == 0) {
            for (int idx = t; idx < JJ * DD; idx += 256)
                g_osum[b * (JJ * DD) + idx] = sO[idx];
        }
        {
            const float4* op = reinterpret_cast<const float4*>(sO);
            #pragma unroll
            for (int m = 0; m < 4; m++) {
                float4 f0 = op[m * 64 + 2 * l], f1 = op[m * 64 + 2 * l + 1];
                ov[m][0] = f0.x; ov[m][1] = f0.y; ov[m][2] = f0.z; ov[m][3] = f0.w;
                ov[m][4] = f1.x; ov[m][5] = f1.y; ov[m][6] = f1.z; ov[m][7] = f1.w;
            }
        }
        __syncthreads();  // sO -> sS reuse safe
    }

    float sacc[4][8];
    #pragma unroll
    for (int m = 0; m < 4; m++)
        #pragma unroll
        for (int k = 0; k < 8; k++) sacc[m][k] = 0.f;

    // per-warp ring: warp w streams i = itile*128 + w*16 + (0..15)
    const char* gw = reinterpret_cast<const char*>(g_U) +
                     ((size_t)b * II + itile * 128 + w * 16) * 2048 +
                     (size_t)l * 16;
    const unsigned sw_lane =
        (unsigned)__cvta_generic_to_shared(sU) + (unsigned)(w * 8192 + l * 16);

    #pragma unroll
    for (int s = 0; s < NSTAGE - 1; s++) {
        #pragma unroll
        for (int k = 0; k < 4; k++)
            cpasync16(sw_lane + (unsigned)(s * 2048 + k * 512),
                      gw + (size_t)s * 2048 + k * 512);
        cpcommit();
    }

    for (int it = 0; it < NITER; it++) {
        cpwait<NSTAGE - 2>();  // this lane's stage `it` resident
        const uint4* p = reinterpret_cast<const uint4*>(
            dsm + w * 8192 + (it & (NSTAGE - 1)) * 2048);
        uint4 r[4];
        #pragma unroll
        for (int m = 0; m < 4; m++) r[m] = p[m * 32 + l];
        route_step<MODE>(r, ov, sacc);
        // commit EVERY iteration (empty in tail) to keep groups aligned
        {
            int s = it + NSTAGE - 1;
            if (s < NITER) {
                #pragma unroll
                for (int k = 0; k < 4; k++)
                    cpasync16(
                        sw_lane + (unsigned)((s & (NSTAGE - 1)) * 2048 + k * 512),
                        gw + (size_t)s * 2048 + k * 512);
            }
            cpcommit();
        }
    }

    // block partial reduce (fixed order -> deterministic)
    float4* sp = reinterpret_cast<float4*>(sS + w * 1024);
    #pragma unroll
    for (int m = 0; m < 4; m++) {
        sp[(m * 32 + l) * 2 + 0] =
            make_float4(sacc[m][0], sacc[m][1], sacc[m][2], sacc[m][3]);
        sp[(m * 32 + l) * 2 + 1] =
            make_float4(sacc[m][4], sacc[m][5], sacc[m][6], sacc[m][7]);
    }
    __syncthreads();
    for (int idx = t; idx < JJ * DD; idx += 256) {
        float v = 0.f;
        #pragma unroll
        for (int ww = 0; ww < 8; ww++) v += sS[ww * 1024 + idx];
        g_spart[DST][itile][b * (JJ * DD) + idx] = v;
    }
}

// ---------------------------------------------------------------------------
// Kernel C: final squash -> out (reads g_spart[0], written by route<2>).
// ---------------------------------------------------------------------------
__global__ void __launch_bounds__(256) squash_kernel(float* __restrict__ out) {
    const int t = threadIdx.x;
    const int bj = blockIdx.x * 8 + (t >> 5);
    const int l = t & 31;
    float v = 0.f;
    #pragma unroll
    for (int it = 0; it < NTILE; it++) v += g_spart[0][it][bj * DD + l];
    float s2 = v * v;
    #pragma unroll
    for (int s = 1; s < 32; s <<= 1) s2 += __shfl_xor_sync(0xffffffffu, s2, s);
    float scale = (s2 / (1.0f + s2)) * rsqrtf(s2 + 1e-7f);
    out[bj * DD + l] = scale * v;
}

// ---------------------------------------------------------------------------
extern "C" void kernel_launch(void* const* d_in, const int* in_sizes, int n_in,
                              void* d_out, int out_size) {
    const float* x;
    const float* W;
    if (in_sizes[0] == BB * II * CC) {
        x = (const float*)d_in[0];
        W = (const float*)d_in[1];
    } else {
        x = (const float*)d_in[1];
        W = (const float*)d_in[0];
    }

    const int uhat_smem = 65536 + BB * CC * (int)sizeof(float);      // 69632
    const int route_smem = 65536 + 8 * 1024 * (int)sizeof(float);    // 98304
    cudaFuncSetAttribute(uhat_kernel, cudaFuncAttributeMaxDynamicSharedMemorySize,
                         uhat_smem);
    cudaFuncSetAttribute((const void*)route_kernel<0, 1, 0, 0>,
                         cudaFuncAttributeMaxDynamicSharedMemorySize, route_smem);
    cudaFuncSetAttribute((const void*)route_kernel<1, 0, 0, 1>,
                         cudaFuncAttributeMaxDynamicSharedMemorySize, route_smem);
    cudaFuncSetAttribute((const void*)route_kernel<2, 1, 1, 0>,
                         cudaFuncAttributeMaxDynamicSharedMemorySize, route_smem);

    float* out = (float*)d_out;
    uhat_kernel<<<II, 256, uhat_smem>>>(x, W);
    route_kernel<0, 1, 0, 0><<<dim3(NTILE, BB), 256, route_smem>>>();
    route_kernel<1, 0, 0, 1><<<dim3(NTILE, BB), 256, route_smem>>>();
    route_kernel<2, 1, 1, 0><<<dim3(NTILE, BB), 256, route_smem>>>();
    squash_kernel<<<BB * JJ / 8, 256>>>(out);
}

// round 9
// speedup vs baseline: 1.0580x; 1.0580x over previous
#include <cuda_runtime.h>
#include <cuda_fp16.h>

// CapsuleLayer dynamic routing, GB300 sm_103a.
// B=64, I=2048, Din=16, J=32, D=32, 3 routing iters.
//
// b_k[b,j,i] = osum_k[b,j,:] . u_hat[b,j,i,:]; each routing iteration is one
// streaming pass over fp16 u_hat ([b][i][j][d]) + tiny squash kernel.
// Iteration 0: c == 1/32 exactly. Softmax without max-subtraction.
// Route passes stream u_hat through a 5-stage block-wide cp.async smem ring
// (explicit rotating indices; a group is committed EVERY iteration, empty in
// the tail, so wait_group<NSTAGE-2> alignment holds through the epilogue).

#define BB 64
#define II 2048
#define CC 16
#define JJ 32
#define DD 32
#define NTILE 16   // i-tiles (blocks) per b; block covers 128 i
#define NSTAGE 5   // cp.async ring stages (8 i = 16KB per stage)
#define NITER 16   // stages per block (128 i / 8)

typedef unsigned long long u64;

__device__ __half g_U[(size_t)BB * II * JJ * DD];   // 256 MB scratch (fp16)
__device__ float g_osum[BB * JJ * DD];              // running output sum
__device__ float g_spart[NTILE][BB * JJ * DD];      // per-itile partial s

// ---------- packed fp32x2 helpers ----------
__device__ __forceinline__ u64 fma2(u64 a, u64 b, u64 c) {
    u64 d;
    asm("fma.rn.f32x2 %0, %1, %2, %3;" : "=l"(d) : "l"(a), "l"(b), "l"(c));
    return d;
}
__device__ __forceinline__ u64 add2(u64 a, u64 b) {
    u64 d;
    asm("add.rn.f32x2 %0, %1, %2;" : "=l"(d) : "l"(a), "l"(b));
    return d;
}
__device__ __forceinline__ float hsum2(u64 v) {
    float a, b;
    asm("mov.b64 {%0, %1}, %2;" : "=f"(a), "=f"(b) : "l"(v));
    return a + b;
}

// ---------- cp.async helpers ----------
__device__ __forceinline__ void cpasync16(unsigned smem_addr, const void* g) {
    asm volatile("cp.async.cg.shared.global [%0], [%1], 16;" ::"r"(smem_addr),
                 "l"(g));
}
__device__ __forceinline__ void cpcommit() {
    asm volatile("cp.async.commit_group;");
}
template <int N>
__device__ __forceinline__ void cpwait() {
    asm volatile("cp.async.wait_group %0;" ::"n"(N));
}

// ---------------------------------------------------------------------------
// Kernel A: u_hat[b][i][j][d] = sum_c W[j][i][d][c] * x[b][i][c], fp16.
// One block per i. W chunk-major in smem (8 contiguous LDS.128 per (j,thread),
// conflict-free). Thread (bg = t>>4, q = t&15): 4 batches, d = 2q, 2q+1.
// (Unchanged from the round-7 273us kernel.)
// ---------------------------------------------------------------------------
__global__ void __launch_bounds__(256, 2)
uhat_kernel(const float* __restrict__ x, const float* __restrict__ W) {
    extern __shared__ __align__(16) char smraw[];
    float2* sW = reinterpret_cast<float2*>(smraw);        // [8][1024] = 64KB
    float* sX = reinterpret_cast<float*>(smraw + 65536);  // [64][16]  = 4KB
    const int i = blockIdx.x;
    const int t = threadIdx.x;

    const float4* Wg = reinterpret_cast<const float4*>(W);
    #pragma unroll
    for (int k = 0; k < 16; k++) {
        int v = t + 256 * k;
        int row = v >> 2, ch = v & 3;  // row = j*32 + d
        int j = row >> 5, d = row & 31;
        float4 f = Wg[(size_t)(j * II + i) * 128 + d * 4 + ch];
        sW[(2 * ch) * 1024 + row] = make_float2(f.x, f.y);
        sW[(2 * ch + 1) * 1024 + row] = make_float2(f.z, f.w);
    }
    {
        int b = t >> 2, r = t & 3;
        reinterpret_cast<float4*>(sX)[t] =
            reinterpret_cast<const float4*>(x)[(size_t)(b * II + i) * 4 + r];
    }
    __syncthreads();

    const int bg = t >> 4, q = t & 15;
    u64 xr[4][8];
    #pragma unroll
    for (int s = 0; s < 4; s++) {
        const u64* xp = reinterpret_cast<const u64*>(sX + (bg + 16 * s) * CC);
        #pragma unroll
        for (int k = 0; k < 8; k++) xr[s][k] = xp[k];
    }

    __half2* Uo = reinterpret_cast<__half2*>(g_U);
    const float4* sW4 = reinterpret_cast<const float4*>(sW);
    for (int j = 0; j < JJ; j++) {
        u64 w0[8], w1[8];
        #pragma unroll
        for (int k = 0; k < 8; k++) {
            float4 wv = sW4[k * 512 + j * 16 + q];
            const u64* pv = reinterpret_cast<const u64*>(&wv);
            w0[k] = pv[0];  // d = 2q
            w1[k] = pv[1];  // d = 2q+1
        }
        #pragma unroll
        for (int s = 0; s < 4; s++) {
            u64 a0 = 0ULL, a1 = 0ULL, b0 = 0ULL, b1 = 0ULL;
            #pragma unroll
            for (int k = 0; k < 8; k += 2) {
                a0 = fma2(w0[k],     xr[s][k],     a0);
                a1 = fma2(w0[k + 1], xr[s][k + 1], a1);
                b0 = fma2(w1[k],     xr[s][k],     b0);
                b1 = fma2(w1[k + 1], xr[s][k + 1], b1);
            }
            float d0 = hsum2(add2(a0, a1));
            float d1 = hsum2(add2(b0, b1));
            int b = bg + 16 * s;
            Uo[(size_t)(b * II + i) * 512 + j * 16 + q] = __floats2half2_rn(d0, d1);
        }
    }
}

// ---------------------------------------------------------------------------
// Route compute step: lane l chunk m (uint4 = 8 halfs) holds j = 8m + (l>>2),
// d-seg (l&3)*8..+7. Logit reduce over 4-lane groups; softmax over 32 j via
// in-thread + xor 4,8,16.
// ---------------------------------------------------------------------------
__device__ __forceinline__ void cvt8(const uint4& r, float* uf) {
    const __half2* h = reinterpret_cast<const __half2*>(&r);
    #pragma unroll
    for (int p = 0; p < 4; p++) {
        float2 f = __half22float2(h[p]);
        uf[2 * p] = f.x;
        uf[2 * p + 1] = f.y;
    }
}

template <int MODE>
__device__ __forceinline__ void route_step(const uint4* r, const float ov[4][8],
                                           float sacc[4][8]) {
    float uf[4][8];
    #pragma unroll
    for (int m = 0; m < 4; m++) cvt8(r[m], uf[m]);
    float c[4];
    if (MODE == 0) {
        #pragma unroll
        for (int m = 0; m < 4; m++) c[m] = 0.03125f;
    } else {
        float tp[4];
        #pragma unroll
        for (int m = 0; m < 4; m++) {
            float a = uf[m][0] * ov[m][0];
            #pragma unroll
            for (int k = 1; k < 8; k++) a = fmaf(uf[m][k], ov[m][k], a);
            tp[m] = a;
        }
        #pragma unroll
        for (int s = 1; s < 4; s <<= 1)
            #pragma unroll
            for (int m = 0; m < 4; m++)
                tp[m] += __shfl_xor_sync(0xffffffffu, tp[m], s);
        float e[4], ss = 0.f;
        #pragma unroll
        for (int m = 0; m < 4; m++) {
            e[m] = __expf(tp[m]);
            ss += e[m];
        }
        ss += __shfl_xor_sync(0xffffffffu, ss, 4);
        ss += __shfl_xor_sync(0xffffffffu, ss, 8);
        ss += __shfl_xor_sync(0xffffffffu, ss, 16);
        float inv = __fdividef(1.0f, ss);
        #pragma unroll
        for (int m = 0; m < 4; m++) c[m] = e[m] * inv;
    }
    #pragma unroll
    for (int m = 0; m < 4; m++)
        #pragma unroll
        for (int k = 0; k < 8; k++) sacc[m][k] = fmaf(c[m], uf[m][k], sacc[m][k]);
}

// ---------------------------------------------------------------------------
// Kernel B: one routing pass with a 5-stage block-wide cp.async pipeline.
// grid = (NTILE, BB), 256 thr. Block streams 128 consecutive i (256 KB) in
// 16-KB stages (8 i); warp w consumes i-slot w of each stage from smem.
// DIR reverses (itile,b) so consecutive passes meet in L2.
// ---------------------------------------------------------------------------
template <int MODE, int DIR>
__global__ void __launch_bounds__(256, 2) route_kernel() {
    extern __shared__ __align__(16) char dsm[];
    __half* sU = reinterpret_cast<__half*>(dsm);                  // NSTAGE*16KB
    float* sS = reinterpret_cast<float*>(dsm + NSTAGE * 16384);   // 8*1024 f

    const int itile = DIR ? (NTILE - 1 - (int)blockIdx.x) : (int)blockIdx.x;
    const int b = DIR ? (BB - 1 - (int)blockIdx.y) : (int)blockIdx.y;
    const int t = threadIdx.x, w = t >> 5, l = t & 31;

    float ov[4][8];
    if (MODE > 0) {
        const float4* op = reinterpret_cast<const float4*>(g_osum + b * (JJ * DD));
        #pragma unroll
        for (int m = 0; m < 4; m++) {
            float4 f0 = op[m * 64 + 2 * l], f1 = op[m * 64 + 2 * l + 1];
            ov[m][0] = f0.x; ov[m][1] = f0.y; ov[m][2] = f0.z; ov[m][3] = f0.w;
            ov[m][4] = f1.x; ov[m][5] = f1.y; ov[m][6] = f1.z; ov[m][7] = f1.w;
        }
    }
    float sacc[4][8];
    #pragma unroll
    for (int m = 0; m < 4; m++)
        #pragma unroll
        for (int k = 0; k < 8; k++) sacc[m][k] = 0.f;

    // per-thread offset t*16 in BOTH shared and global addresses
    const char* gbt = reinterpret_cast<const char*>(g_U) +
                      ((size_t)b * II + itile * 128) * 2048 + (size_t)t * 16;
    const unsigned su_base =
        (unsigned)__cvta_generic_to_shared(sU) + (unsigned)(t * 16);

    // prologue: issue stages 0..NSTAGE-2
    #pragma unroll
    for (int s = 0; s < NSTAGE - 1; s++) {
        #pragma unroll
        for (int k = 0; k < 4; k++)
            cpasync16(su_base + (unsigned)(s * 16384 + k * 4096),
                      gbt + (size_t)s * 16384 + k * 4096);
        cpcommit();
    }

    int rd = 0;           // stage being consumed this iteration
    int wr = NSTAGE - 1;  // stage slot to fill next
    for (int it = 0; it < NITER; it++) {
        cpwait<NSTAGE - 2>();  // stage rd resident (groups stay aligned)
        __syncthreads();
        const uint4* p =
            reinterpret_cast<const uint4*>(sU + rd * 8192 + w * 1024);
        uint4 r[4];
        #pragma unroll
        for (int m = 0; m < 4; m++) r[m] = p[m * 32 + l];
        route_step<MODE>(r, ov, sacc);
        __syncthreads();  // everyone done with this buffer
        // Commit EVERY iteration (empty group in the tail) so wait_group
        // always forces completion of the stage consumed NSTAGE-1 iters later.
        {
            int s = it + NSTAGE - 1;
            if (s < NITER) {
                #pragma unroll
                for (int k = 0; k < 4; k++)
                    cpasync16(su_base + (unsigned)(wr * 16384 + k * 4096),
                              gbt + (size_t)s * 16384 + k * 4096);
            }
            cpcommit();
        }
        if (++rd == NSTAGE) rd = 0;
        if (++wr == NSTAGE) wr = 0;
    }

    // block partial reduce (fixed order -> deterministic)
    float4* sp = reinterpret_cast<float4*>(sS + w * 1024);
    #pragma unroll
    for (int m = 0; m < 4; m++) {
        sp[(m * 32 + l) * 2 + 0] =
            make_float4(sacc[m][0], sacc[m][1], sacc[m][2], sacc[m][3]);
        sp[(m * 32 + l) * 2 + 1] =
            make_float4(sacc[m][4], sacc[m][5], sacc[m][6], sacc[m][7]);
    }
    __syncthreads();
    for (int idx = t; idx < JJ * DD; idx += 256) {
        float v = 0.f;
        #pragma unroll
        for (int ww = 0; ww < 8; ww++) v += sS[ww * 1024 + idx];
        g_spart[itile][b * (JJ * DD) + idx] = v;
    }
}

// ---------------------------------------------------------------------------
// Kernel C: reduce itile partials, squash, update osum / write final out.
// mode 0: osum = o ; mode 1: osum += o ; mode 2: out = o.
// ---------------------------------------------------------------------------
__global__ void __launch_bounds__(256) squash_kernel(float* __restrict__ out,
                                                     int mode) {
    const int t = threadIdx.x;
    const int bj = blockIdx.x * 8 + (t >> 5);
    const int l = t & 31;
    float v = 0.f;
    #pragma unroll
    for (int it = 0; it < NTILE; it++) v += g_spart[it][bj * DD + l];
    float s2 = v * v;
    #pragma unroll
    for (int s = 1; s < 32; s <<= 1) s2 += __shfl_xor_sync(0xffffffffu, s2, s);
    float scale = (s2 / (1.0f + s2)) * rsqrtf(s2 + 1e-7f);
    float o = scale * v;
    if (mode == 2)
        out[bj * DD + l] = o;
    else if (mode == 1)
        g_osum[bj * DD + l] += o;
    else
        g_osum[bj * DD + l] = o;
}

// ---------------------------------------------------------------------------
extern "C" void kernel_launch(void* const* d_in, const int* in_sizes, int n_in,
                              void* d_out, int out_size) {
    const float* x;
    const float* W;
    if (in_sizes[0] == BB * II * CC) {
        x = (const float*)d_in[0];
        W = (const float*)d_in[1];
    } else {
        x = (const float*)d_in[1];
        W = (const float*)d_in[0];
    }

    const int uhat_smem = 65536 + BB * CC * (int)sizeof(float);            // 69632
    const int route_smem = NSTAGE * 16384 + 8 * 1024 * (int)sizeof(float); // 114688
    cudaFuncSetAttribute(uhat_kernel, cudaFuncAttributeMaxDynamicSharedMemorySize,
                         uhat_smem);
    cudaFuncSetAttribute(route_kernel<0, 1>,
                         cudaFuncAttributeMaxDynamicSharedMemorySize, route_smem);
    cudaFuncSetAttribute(route_kernel<1, 0>,
                         cudaFuncAttributeMaxDynamicSharedMemorySize, route_smem);
    cudaFuncSetAttribute(route_kernel<2, 1>,
                         cudaFuncAttributeMaxDynamicSharedMemorySize, route_smem);

    float* out = (float*)d_out;
    uhat_kernel<<<II, 256, uhat_smem>>>(x, W);
    route_kernel<0, 1><<<dim3(NTILE, BB), 256, route_smem>>>();
    squash_kernel<<<BB * JJ / 8, 256>>>(out, 0);
    route_kernel<1, 0><<<dim3(NTILE, BB), 256, route_smem>>>();
    squash_kernel<<<BB * JJ / 8, 256>>>(out, 1);
    route_kernel<2, 1><<<dim3(NTILE, BB), 256, route_smem>>>();
    squash_kernel<<<BB * JJ / 8, 256>>>(out, 2);
}